// round 10
// baseline (speedup 1.0000x reference)
#include <cuda_runtime.h>
#include <cuda_fp16.h>
#include <cstdint>

// Problem shape (fixed): B=2, S=2048 -> ROWS=4096, n=m=4096
#define ROWS_T 4096
#define NDIM   4096
#define MDIM   4096
#define NCODE  (MDIM * (NDIM / 8))   // 2,097,152 codewords

// Scratch (allocation-free rule: __device__ globals)
__device__ __half g_Xh[(size_t)ROWS_T * NDIM];        // fp16 rotated input
__device__ __half g_W [(size_t)MDIM   * NDIM];        // fp16 dequantized weights
__device__ __half g_P [2 * (size_t)ROWS_T * MDIM];    // fp16 split-K partial products

// ===========================================================================
// helpers
// ===========================================================================
__device__ __forceinline__ uint32_t smem_u32(const void* p) {
    uint32_t a;
    asm("{ .reg .u64 t; cvta.to.shared.u64 t, %1; cvt.u32.u64 %0, t; }" : "=r"(a) : "l"(p));
    return a;
}
__device__ __forceinline__ void cp_async16(uint32_t dst, const void* src) {
    asm volatile("cp.async.cg.shared.global [%0], [%1], 16;\n" :: "r"(dst), "l"(src));
}
#define CP_COMMIT() asm volatile("cp.async.commit_group;\n")
#define CP_WAIT1()  asm volatile("cp.async.wait_group 1;\n" ::: "memory")

#define SWZ(b) ((b) ^ (((b) >> 3) & 0x70))

#define LDSM4(r0, r1, r2, r3, addr) \
    asm volatile("ldmatrix.sync.aligned.m8n8.x4.shared.b16 {%0,%1,%2,%3}, [%4];" \
        : "=r"(r0), "=r"(r1), "=r"(r2), "=r"(r3) : "r"(addr))

#define MMA16816(d, a, b0, b1) \
    asm volatile("mma.sync.aligned.m16n8k16.row.col.f32.f16.f16.f32 " \
        "{%0,%1,%2,%3}, {%4,%5,%6,%7}, {%8,%9}, {%0,%1,%2,%3};" \
        : "+f"((d)[0]), "+f"((d)[1]), "+f"((d)[2]), "+f"((d)[3]) \
        : "r"((a)[0]), "r"((a)[1]), "r"((a)[2]), "r"((a)[3]), "r"(b0), "r"(b1))

// ===========================================================================
// Kernel 1: W = fp16( grid[Qidxs].reshape(m, n) )   (standalone, no smem)
// ===========================================================================
__global__ void dequant_kernel(const float* __restrict__ grid,
                               const int*   __restrict__ qidxs,
                               __half*      __restrict__ W) {
    int i = blockIdx.x * blockDim.x + threadIdx.x;
    if (i >= NCODE) return;
    int idx = qidxs[i];
    const float4* g4 = reinterpret_cast<const float4*>(grid) + (size_t)idx * 2;
    float4 a = g4[0], b = g4[1];
    __half2 h0 = __floats2half2_rn(a.x, a.y);
    __half2 h1 = __floats2half2_rn(a.z, a.w);
    __half2 h2 = __floats2half2_rn(b.x, b.y);
    __half2 h3 = __floats2half2_rn(b.z, b.w);
    uint4 o;
    o.x = *reinterpret_cast<uint32_t*>(&h0);
    o.y = *reinterpret_cast<uint32_t*>(&h1);
    o.z = *reinterpret_cast<uint32_t*>(&h2);
    o.w = *reinterpret_cast<uint32_t*>(&h3);
    reinterpret_cast<uint4*>(W)[i] = o;
}

// ===========================================================================
// FWHT radix-16 butterfly on 16 registers
// ===========================================================================
__device__ __forceinline__ void fwht16(float v[16]) {
    #pragma unroll
    for (int h = 1; h < 16; h <<= 1) {
        #pragma unroll
        for (int j = 0; j < 16; j += 2 * h) {
            #pragma unroll
            for (int k = 0; k < h; k++) {
                float a = v[j + k], b = v[j + k + h];
                v[j + k]     = a + b;
                v[j + k + h] = a - b;
            }
        }
    }
}

// Shared FWHT core: 3 passes + final transpose so the caller reads/writes
// CONTIGUOUS 16-element runs per thread (fully vectorized global access).
// Pad: phys(e) = e + (e>>4); conflict-free for 17-, 272-stride and contiguous.
__device__ __forceinline__ void fwht4096_core(float v[16], float* s, int t) {
    fwht16(v);                                   // bits 0-3 (contiguous 16)
    #pragma unroll
    for (int i = 0; i < 16; i++) s[17 * t + i] = v[i];
    __syncthreads();
    const int r = t & 15, q = t >> 4;
    const int b2 = 272 * q + r;
    #pragma unroll
    for (int i = 0; i < 16; i++) v[i] = s[b2 + 17 * i];
    fwht16(v);                                   // bits 4-7
    #pragma unroll
    for (int i = 0; i < 16; i++) s[b2 + 17 * i] = v[i];
    __syncthreads();
    const int b3 = t + (t >> 4);
    #pragma unroll
    for (int i = 0; i < 16; i++) v[i] = s[b3 + 272 * i];
    fwht16(v);                                   // bits 8-11
    __syncthreads();                             // protect s before reuse
    #pragma unroll
    for (int i = 0; i < 16; i++) s[b3 + 272 * i] = v[i];   // transpose back
    __syncthreads();
    #pragma unroll
    for (int i = 0; i < 16; i++) v[i] = s[17 * t + i];     // contiguous again
}

// ===========================================================================
// Kernel 2: Xh[row] = fp16( FWHT(input[row] * SU) / 64 ), coalesced halves out
// ===========================================================================
__global__ __launch_bounds__(256)
void fwht_su_kernel(const float* __restrict__ in,
                    const float* __restrict__ su,
                    __half*      __restrict__ out) {
    __shared__ float s[4096 + 256];
    const int t = threadIdx.x;
    const size_t row = blockIdx.x;
    float v[16];
    const float4* in4 = reinterpret_cast<const float4*>(in + row * NDIM) + t * 4;
    const float4* su4 = reinterpret_cast<const float4*>(su) + t * 4;
    #pragma unroll
    for (int i = 0; i < 4; i++) {
        float4 a = in4[i], b = su4[i];
        v[4*i+0] = a.x * b.x; v[4*i+1] = a.y * b.y;
        v[4*i+2] = a.z * b.z; v[4*i+3] = a.w * b.w;
    }
    fwht4096_core(v, s, t);
    // contiguous fp16 stores: 16 halves = 2 x uint4
    uint4 o[2];
    #pragma unroll
    for (int j = 0; j < 2; j++) {
        __half2 h0 = __floats2half2_rn(v[8*j+0] * 0.015625f, v[8*j+1] * 0.015625f);
        __half2 h1 = __floats2half2_rn(v[8*j+2] * 0.015625f, v[8*j+3] * 0.015625f);
        __half2 h2 = __floats2half2_rn(v[8*j+4] * 0.015625f, v[8*j+5] * 0.015625f);
        __half2 h3 = __floats2half2_rn(v[8*j+6] * 0.015625f, v[8*j+7] * 0.015625f);
        o[j].x = *reinterpret_cast<uint32_t*>(&h0);
        o[j].y = *reinterpret_cast<uint32_t*>(&h1);
        o[j].z = *reinterpret_cast<uint32_t*>(&h2);
        o[j].w = *reinterpret_cast<uint32_t*>(&h3);
    }
    uint4* op = reinterpret_cast<uint4*>(out + row * NDIM + 16 * t);
    op[0] = o[0]; op[1] = o[1];
}

// ===========================================================================
// Kernel 4: out = FWHT(P0 + P1) * SV / 64   (reads fp16 partials, fp32 out)
// ===========================================================================
__global__ __launch_bounds__(256)
void fwht_sv_kernel(const __half* __restrict__ P,
                    float*        __restrict__ out,
                    const float*  __restrict__ sv) {
    __shared__ float s[4096 + 256];
    const int t = threadIdx.x;
    const size_t row = blockIdx.x;
    float v[16];
    const uint4* p0 = reinterpret_cast<const uint4*>(P + row * MDIM) + 2 * t;
    const uint4* p1 = reinterpret_cast<const uint4*>(P + (size_t)ROWS_T * MDIM + row * MDIM) + 2 * t;
    #pragma unroll
    for (int j = 0; j < 2; j++) {
        uint4 a = p0[j], b = p1[j];
        const __half2* ah = reinterpret_cast<const __half2*>(&a);
        const __half2* bh = reinterpret_cast<const __half2*>(&b);
        #pragma unroll
        for (int k = 0; k < 4; k++) {
            float2 fa = __half22float2(ah[k]);
            float2 fb = __half22float2(bh[k]);
            v[8*j + 2*k + 0] = fa.x + fb.x;
            v[8*j + 2*k + 1] = fa.y + fb.y;
        }
    }
    fwht4096_core(v, s, t);
    // contiguous fp32 stores with SV * 1/64
    const float4* sv4 = reinterpret_cast<const float4*>(sv) + 4 * t;
    float4* op = reinterpret_cast<float4*>(out + row * MDIM + 16 * t);
    #pragma unroll
    for (int i = 0; i < 4; i++) {
        float4 sc = sv4[i];
        op[i] = make_float4(v[4*i+0] * sc.x * 0.015625f,
                            v[4*i+1] * sc.y * 0.015625f,
                            v[4*i+2] * sc.z * 0.015625f,
                            v[4*i+3] * sc.w * 0.015625f);
    }
}

// ===========================================================================
// Kernel 3: fp16 mma.sync GEMM, split-K=2.
// CTA tile 128x128x64; 4 warps (2M x 2N), warp tile 64x64; K half = 2048.
// Partials written fp16 to g_P plane z. 2048 CTAs -> 98.9% tail efficiency.
// ===========================================================================
#define NST      3
#define A_ST     (128 * 128)
#define B_ST     (128 * 128)
#define STG      (A_ST + B_ST)        // 32 KB
#define GEMM_SMEM (NST * STG + 1024)  // 97 KB -> 2 CTAs/SM

__device__ __forceinline__ void load_stage(uint32_t s0, int st, int kt, int tid,
                                           const __half* Ab, const __half* Bb) {
    uint32_t sA = s0 + st * STG;
    uint32_t sB = sA + A_ST;
    #pragma unroll
    for (int it = 0; it < 16; it++) {
        int c = tid + it * 128;                  // 0..2047
        if (c < 1024) {                          // A: 128 rows x 8 chunks(16B)
            int rr = c >> 3, cc = c & 7;
            cp_async16(sA + SWZ(rr * 128 + cc * 16),
                       Ab + (size_t)rr * NDIM + kt * 64 + cc * 8);
        } else {                                 // B
            int b = c - 1024;
            int rr = b >> 3, cc = b & 7;
            cp_async16(sB + SWZ(rr * 128 + cc * 16),
                       Bb + (size_t)rr * NDIM + kt * 64 + cc * 8);
        }
    }
    CP_COMMIT();
}

__global__ __launch_bounds__(128, 2)
void gemm_fp16(const __half* __restrict__ A,
               const __half* __restrict__ B,
               __half*       __restrict__ P) {
    extern __shared__ char smraw[];
    const uint32_t s0 = (smem_u32(smraw) + 1023u) & ~1023u;
    const int tid  = threadIdx.x;
    const int wid  = tid >> 5;
    const int lane = tid & 31;
    const int g    = lane >> 2;
    const int t4   = lane & 3;
    const int wm   = (wid & 1) * 64;
    const int wn   = (wid >> 1) * 64;

    const int a_row = (lane & 7) + ((lane & 8)  ? 8 : 0);
    const int a_kx  = (lane & 16) ? 16 : 0;
    const int b_row = (lane & 7) + ((lane & 16) ? 8 : 0);
    const int b_kx  = (lane & 8)  ? 16 : 0;

    const int kz = blockIdx.z * (NDIM / 2);      // split-K half offset (elems)
    const __half* Ab = A + (size_t)(blockIdx.y * 128) * NDIM + kz;
    const __half* Bb = B + (size_t)(blockIdx.x * 128) * NDIM + kz;

    float c[4][8][4];
    #pragma unroll
    for (int i = 0; i < 4; i++)
        #pragma unroll
        for (int j = 0; j < 8; j++)
            #pragma unroll
            for (int k = 0; k < 4; k++) c[i][j][k] = 0.f;

    uint32_t af[2][4][4], bf[2][8][2];

    #define LOAD_FRAGS(buf, base, kb) do {                                      \
        const uint32_t _sA = (base);                                            \
        const uint32_t _sB = _sA + A_ST;                                        \
        _Pragma("unroll")                                                       \
        for (int mi = 0; mi < 4; mi++) {                                        \
            int row = wm + mi * 16 + a_row;                                     \
            uint32_t ad = _sA + row * 128 + (((kb) + a_kx) ^ ((row & 7) << 4)); \
            LDSM4(af[buf][mi][0], af[buf][mi][1], af[buf][mi][2], af[buf][mi][3], ad); \
        }                                                                       \
        _Pragma("unroll")                                                       \
        for (int nb = 0; nb < 4; nb++) {                                        \
            int row = wn + nb * 16 + b_row;                                     \
            uint32_t bd = _sB + row * 128 + (((kb) + b_kx) ^ ((row & 7) << 4)); \
            LDSM4(bf[buf][2*nb][0], bf[buf][2*nb][1],                           \
                  bf[buf][2*nb+1][0], bf[buf][2*nb+1][1], bd);                  \
        }                                                                       \
    } while (0)

    load_stage(s0, 0, 0, tid, Ab, Bb);
    load_stage(s0, 1, 1, tid, Ab, Bb);
    CP_WAIT1();
    __syncthreads();
    LOAD_FRAGS(0, s0, 0);

    const int KT = (NDIM / 2) / 64;   // 32 k-tiles per split
    for (int kt = 0; kt < KT; kt++) {
        const uint32_t stage_cur = s0 + (kt % NST) * STG;
        const uint32_t stage_nxt = s0 + ((kt + 1) % NST) * STG;
        #pragma unroll
        for (int ks = 0; ks < 4; ks++) {
            const int cur = ks & 1, nxt = cur ^ 1;
            if (ks == 3) {
                if (kt + 1 < KT) {
                    CP_WAIT1();
                    __syncthreads();
                    LOAD_FRAGS(nxt, stage_nxt, 0);
                }
            } else {
                LOAD_FRAGS(nxt, stage_cur, (ks + 1) * 32);
            }
            if (ks == 0) {
                if (kt + 2 < KT) load_stage(s0, (kt + 2) % NST, kt + 2, tid, Ab, Bb);
                else             CP_COMMIT();
            }
            #pragma unroll
            for (int mi = 0; mi < 4; mi++)
                #pragma unroll
                for (int ni = 0; ni < 8; ni++)
                    MMA16816(c[mi][ni], af[cur][mi], bf[cur][ni][0], bf[cur][ni][1]);
        }
    }
    #undef LOAD_FRAGS

    // epilogue: fp16 partials to plane z
    __half* Cb = P + (size_t)blockIdx.z * ROWS_T * MDIM
                   + (size_t)(blockIdx.y * 128 + wm) * MDIM + blockIdx.x * 128 + wn;
    #pragma unroll
    for (int mi = 0; mi < 4; mi++) {
        #pragma unroll
        for (int ni = 0; ni < 8; ni++) {
            const int col = ni * 8 + 2 * t4;
            __half2 h0 = __floats2half2_rn(c[mi][ni][0], c[mi][ni][1]);
            __half2 h1 = __floats2half2_rn(c[mi][ni][2], c[mi][ni][3]);
            *reinterpret_cast<__half2*>(Cb + (size_t)(mi * 16 + g    ) * MDIM + col) = h0;
            *reinterpret_cast<__half2*>(Cb + (size_t)(mi * 16 + g + 8) * MDIM + col) = h1;
        }
    }
}

// ===========================================================================
// Launch: input, SU, SV, grid, Qidxs (metadata order)
// ===========================================================================
extern "C" void kernel_launch(void* const* d_in, const int* in_sizes, int n_in,
                              void* d_out, int out_size) {
    const float* input = (const float*)d_in[0];
    const float* SU    = (const float*)d_in[1];
    const float* SV    = (const float*)d_in[2];
    const float* grid  = (const float*)d_in[3];
    const int*   qidxs = (const int*)  d_in[4];
    float* out = (float*)d_out;

    __half* Xh = nullptr;
    __half* W  = nullptr;
    __half* P  = nullptr;
    cudaGetSymbolAddress((void**)&Xh, g_Xh);
    cudaGetSymbolAddress((void**)&W,  g_W);
    cudaGetSymbolAddress((void**)&P,  g_P);

    cudaFuncSetAttribute(gemm_fp16, cudaFuncAttributeMaxDynamicSharedMemorySize, GEMM_SMEM);

    // 1. dequantize codebook -> W (fp16)
    dequant_kernel<<<NCODE / 256, 256>>>(grid, qidxs, W);

    // 2. Xh = fp16( FWHT(input * SU) / 64 )
    fwht_su_kernel<<<ROWS_T, 256>>>(input, SU, Xh);

    // 3. P[z] = Xh @ W^T over K half z   (fp16 mma.sync, fp32 accum, split-K=2)
    dim3 gdim(MDIM / 128, ROWS_T / 128, 2);
    gemm_fp16<<<gdim, 128, GEMM_SMEM>>>(Xh, W, P);

    // 4. out = FWHT(P0 + P1) * SV / 64
    fwht_sv_kernel<<<ROWS_T, 256>>>(P, out, SV);
}

// round 11
// speedup vs baseline: 1.0692x; 1.0692x over previous
#include <cuda_runtime.h>
#include <cuda_fp16.h>
#include <cstdint>

// Problem shape (fixed): B=2, S=2048 -> ROWS=4096, n=m=4096
#define ROWS_T 4096
#define NDIM   4096
#define MDIM   4096
#define NCODE  (MDIM * (NDIM / 8))   // 2,097,152 codewords

// Tail-split geometry: tile-rows 0..17 full-K; tile-rows 18..31 split-K=4
#define FULL_TILES   576              // 18 rows x 32 cols
#define TAIL_TILES   448              // 14 rows x 32 cols
#define TAIL_ROW0    2304             // 18 * 128
#define TAIL_ROWS    1792             // 14 * 128
#define QK           1024             // K per quarter chunk

// Scratch (allocation-free rule: __device__ globals)
__device__ __half g_Xh[(size_t)ROWS_T * NDIM];              // fp16 rotated input
__device__ __half g_W [(size_t)MDIM   * NDIM];              // fp16 dequantized weights
__device__ __half g_P [4 * (size_t)TAIL_ROWS * MDIM];       // fp16 split-K partials (tail rows)

// ===========================================================================
// helpers
// ===========================================================================
__device__ __forceinline__ uint32_t smem_u32(const void* p) {
    uint32_t a;
    asm("{ .reg .u64 t; cvta.to.shared.u64 t, %1; cvt.u32.u64 %0, t; }" : "=r"(a) : "l"(p));
    return a;
}
__device__ __forceinline__ void cp_async16(uint32_t dst, const void* src) {
    asm volatile("cp.async.cg.shared.global [%0], [%1], 16;\n" :: "r"(dst), "l"(src));
}
#define CP_COMMIT() asm volatile("cp.async.commit_group;\n")
#define CP_WAIT1()  asm volatile("cp.async.wait_group 1;\n" ::: "memory")

#define SWZ(b) ((b) ^ (((b) >> 3) & 0x70))

#define LDSM4(r0, r1, r2, r3, addr) \
    asm volatile("ldmatrix.sync.aligned.m8n8.x4.shared.b16 {%0,%1,%2,%3}, [%4];" \
        : "=r"(r0), "=r"(r1), "=r"(r2), "=r"(r3) : "r"(addr))

#define MMA16816(d, a, b0, b1) \
    asm volatile("mma.sync.aligned.m16n8k16.row.col.f32.f16.f16.f32 " \
        "{%0,%1,%2,%3}, {%4,%5,%6,%7}, {%8,%9}, {%0,%1,%2,%3};" \
        : "+f"((d)[0]), "+f"((d)[1]), "+f"((d)[2]), "+f"((d)[3]) \
        : "r"((a)[0]), "r"((a)[1]), "r"((a)[2]), "r"((a)[3]), "r"(b0), "r"(b1))

// ===========================================================================
// Kernel 1: W = fp16( grid[Qidxs].reshape(m, n) ), 2 codewords/thread (MLP=2)
// ===========================================================================
__global__ void dequant_kernel(const float* __restrict__ grid,
                               const int*   __restrict__ qidxs,
                               __half*      __restrict__ W) {
    int i0 = (blockIdx.x * blockDim.x + threadIdx.x) * 2;
    #pragma unroll
    for (int u = 0; u < 2; u++) {
        int i = i0 + u;
        int idx = qidxs[i];
        const float4* g4 = reinterpret_cast<const float4*>(grid) + (size_t)idx * 2;
        float4 a = g4[0], b = g4[1];
        __half2 h0 = __floats2half2_rn(a.x, a.y);
        __half2 h1 = __floats2half2_rn(a.z, a.w);
        __half2 h2 = __floats2half2_rn(b.x, b.y);
        __half2 h3 = __floats2half2_rn(b.z, b.w);
        uint4 o;
        o.x = *reinterpret_cast<uint32_t*>(&h0);
        o.y = *reinterpret_cast<uint32_t*>(&h1);
        o.z = *reinterpret_cast<uint32_t*>(&h2);
        o.w = *reinterpret_cast<uint32_t*>(&h3);
        reinterpret_cast<uint4*>(W)[i] = o;
    }
}

// ===========================================================================
// FWHT radix-16 butterfly on 16 registers
// ===========================================================================
__device__ __forceinline__ void fwht16(float v[16]) {
    #pragma unroll
    for (int h = 1; h < 16; h <<= 1) {
        #pragma unroll
        for (int j = 0; j < 16; j += 2 * h) {
            #pragma unroll
            for (int k = 0; k < h; k++) {
                float a = v[j + k], b = v[j + k + h];
                v[j + k]     = a + b;
                v[j + k + h] = a - b;
            }
        }
    }
}

// ===========================================================================
// Kernel 2: Xh[row] = fp16( FWHT(input[row] * SU) / 64 )   (R8-proven core)
// ===========================================================================
__global__ __launch_bounds__(256)
void fwht_su_kernel(const float* __restrict__ in,
                    const float* __restrict__ su,
                    __half*      __restrict__ out) {
    __shared__ float s[4096 + 256];
    const int t = threadIdx.x;
    const size_t row = blockIdx.x;
    float v[16];
    const float4* in4 = reinterpret_cast<const float4*>(in + row * NDIM) + t * 4;
    const float4* su4 = reinterpret_cast<const float4*>(su) + t * 4;
    #pragma unroll
    for (int i = 0; i < 4; i++) {
        float4 a = in4[i], b = su4[i];
        v[4*i+0] = a.x * b.x; v[4*i+1] = a.y * b.y;
        v[4*i+2] = a.z * b.z; v[4*i+3] = a.w * b.w;
    }
    fwht16(v);                                   // bits 0-3
    #pragma unroll
    for (int i = 0; i < 16; i++) s[17 * t + i] = v[i];
    __syncthreads();
    const int r = t & 15, q = t >> 4;
    const int b2 = 272 * q + r;
    #pragma unroll
    for (int i = 0; i < 16; i++) v[i] = s[b2 + 17 * i];
    fwht16(v);                                   // bits 4-7
    #pragma unroll
    for (int i = 0; i < 16; i++) s[b2 + 17 * i] = v[i];
    __syncthreads();
    const int b3 = t + (t >> 4);
    #pragma unroll
    for (int i = 0; i < 16; i++) v[i] = s[b3 + 272 * i];
    fwht16(v);                                   // bits 8-11
    __half* o = out + row * NDIM + t;
    #pragma unroll
    for (int i = 0; i < 16; i++) o[256 * i] = __float2half_rn(v[i] * 0.015625f);
}

// ===========================================================================
// Kernel 4: out = FWHT(C or sum of 4 fp16 partial planes) * SV / 64
// Rows <  TAIL_ROW0 : read fp32 C directly.
// Rows >= TAIL_ROW0 : deterministic fixed-order sum of the 4 partial planes.
// ===========================================================================
__global__ __launch_bounds__(256)
void fwht_sv_kernel(const float*  __restrict__ C,
                    const __half* __restrict__ P,
                    float*        __restrict__ out,
                    const float*  __restrict__ sv) {
    __shared__ float s[4096 + 256];
    const int t = threadIdx.x;
    const size_t row = blockIdx.x;
    float v[16];
    if (row < TAIL_ROW0) {
        const float4* d4 = reinterpret_cast<const float4*>(C + row * MDIM) + t * 4;
        #pragma unroll
        for (int i = 0; i < 4; i++) {
            float4 a = d4[i];
            v[4*i+0] = a.x; v[4*i+1] = a.y; v[4*i+2] = a.z; v[4*i+3] = a.w;
        }
    } else {
        const size_t r2 = row - TAIL_ROW0;
        #pragma unroll
        for (int i = 0; i < 16; i++) v[i] = 0.f;
        #pragma unroll
        for (int z = 0; z < 4; z++) {     // fixed order -> deterministic
            const uint4* pz = reinterpret_cast<const uint4*>(
                P + (size_t)z * TAIL_ROWS * MDIM + r2 * MDIM) + 2 * t;
            #pragma unroll
            for (int j = 0; j < 2; j++) {
                uint4 a = pz[j];
                const __half2* ah = reinterpret_cast<const __half2*>(&a);
                #pragma unroll
                for (int k = 0; k < 4; k++) {
                    float2 fa = __half22float2(ah[k]);
                    v[8*j + 2*k + 0] += fa.x;
                    v[8*j + 2*k + 1] += fa.y;
                }
            }
        }
    }
    fwht16(v);
    #pragma unroll
    for (int i = 0; i < 16; i++) s[17 * t + i] = v[i];
    __syncthreads();
    const int r = t & 15, q = t >> 4;
    const int b2 = 272 * q + r;
    #pragma unroll
    for (int i = 0; i < 16; i++) v[i] = s[b2 + 17 * i];
    fwht16(v);
    #pragma unroll
    for (int i = 0; i < 16; i++) s[b2 + 17 * i] = v[i];
    __syncthreads();
    const int b3 = t + (t >> 4);
    #pragma unroll
    for (int i = 0; i < 16; i++) v[i] = s[b3 + 272 * i];
    fwht16(v);
    float* o = out + row * MDIM + t;
    const float* svp = sv + t;
    #pragma unroll
    for (int i = 0; i < 16; i++) o[256 * i] = v[i] * svp[256 * i] * 0.015625f;
}

// ===========================================================================
// Kernel 3: fp16 mma.sync GEMM with tail-only split-K=4.
// 1D grid, 2368 CTAs:
//   bid <  576 : full tile (y=bid/32, x=bid%32), K=4096, fp32 -> C
//   bid >= 576 : quarter   (q=e%448 -> y=18+q/32, x=q%32; z=e/448), K=1024,
//                fp16 partial -> plane z
// Fulls launch first -> they own wave 1; quarters pack the tail (98.8% eff).
// ===========================================================================
#define NST      3
#define A_ST     (128 * 128)
#define B_ST     (128 * 128)
#define STG      (A_ST + B_ST)        // 32 KB
#define GEMM_SMEM (NST * STG + 1024)  // 97 KB -> 2 CTAs/SM

__device__ __forceinline__ void load_stage(uint32_t s0, int st, int kt, int tid,
                                           const __half* Ab, const __half* Bb) {
    uint32_t sA = s0 + st * STG;
    uint32_t sB = sA + A_ST;
    #pragma unroll
    for (int it = 0; it < 16; it++) {
        int c = tid + it * 128;                  // 0..2047
        if (c < 1024) {                          // A: 128 rows x 8 chunks(16B)
            int rr = c >> 3, cc = c & 7;
            cp_async16(sA + SWZ(rr * 128 + cc * 16),
                       Ab + (size_t)rr * NDIM + kt * 64 + cc * 8);
        } else {                                 // B
            int b = c - 1024;
            int rr = b >> 3, cc = b & 7;
            cp_async16(sB + SWZ(rr * 128 + cc * 16),
                       Bb + (size_t)rr * NDIM + kt * 64 + cc * 8);
        }
    }
    CP_COMMIT();
}

__global__ __launch_bounds__(128, 2)
void gemm_fp16(const __half* __restrict__ A,
               const __half* __restrict__ B,
               float*        __restrict__ C,
               __half*       __restrict__ P) {
    extern __shared__ char smraw[];
    const uint32_t s0 = (smem_u32(smraw) + 1023u) & ~1023u;
    const int tid  = threadIdx.x;
    const int wid  = tid >> 5;
    const int lane = tid & 31;
    const int g    = lane >> 2;
    const int t4   = lane & 3;
    const int wm   = (wid & 1) * 64;
    const int wn   = (wid >> 1) * 64;

    const int a_row = (lane & 7) + ((lane & 8)  ? 8 : 0);
    const int a_kx  = (lane & 16) ? 16 : 0;
    const int b_row = (lane & 7) + ((lane & 16) ? 8 : 0);
    const int b_kx  = (lane & 8)  ? 16 : 0;

    // ---- decode work item ----
    const int bid = blockIdx.x;
    int tx, ty, zq, KT, kbase;
    if (bid < FULL_TILES) {
        tx = bid & 31; ty = bid >> 5; zq = -1;
        KT = NDIM / 64; kbase = 0;
    } else {
        int e = bid - FULL_TILES;
        zq = e / TAIL_TILES;                  // 0..3
        int qd = e - zq * TAIL_TILES;         // 0..447
        tx = qd & 31; ty = 18 + (qd >> 5);
        KT = QK / 64; kbase = zq * QK;
    }

    const __half* Ab = A + (size_t)(ty * 128) * NDIM + kbase;
    const __half* Bb = B + (size_t)(tx * 128) * NDIM + kbase;

    float c[4][8][4];
    #pragma unroll
    for (int i = 0; i < 4; i++)
        #pragma unroll
        for (int j = 0; j < 8; j++)
            #pragma unroll
            for (int k = 0; k < 4; k++) c[i][j][k] = 0.f;

    uint32_t af[2][4][4], bf[2][8][2];

    #define LOAD_FRAGS(buf, base, kb) do {                                      \
        const uint32_t _sA = (base);                                            \
        const uint32_t _sB = _sA + A_ST;                                        \
        _Pragma("unroll")                                                       \
        for (int mi = 0; mi < 4; mi++) {                                        \
            int row = wm + mi * 16 + a_row;                                     \
            uint32_t ad = _sA + row * 128 + (((kb) + a_kx) ^ ((row & 7) << 4)); \
            LDSM4(af[buf][mi][0], af[buf][mi][1], af[buf][mi][2], af[buf][mi][3], ad); \
        }                                                                       \
        _Pragma("unroll")                                                       \
        for (int nb = 0; nb < 4; nb++) {                                        \
            int row = wn + nb * 16 + b_row;                                     \
            uint32_t bd = _sB + row * 128 + (((kb) + b_kx) ^ ((row & 7) << 4)); \
            LDSM4(bf[buf][2*nb][0], bf[buf][2*nb][1],                           \
                  bf[buf][2*nb+1][0], bf[buf][2*nb+1][1], bd);                  \
        }                                                                       \
    } while (0)

    load_stage(s0, 0, 0, tid, Ab, Bb);
    load_stage(s0, 1, 1, tid, Ab, Bb);
    CP_WAIT1();
    __syncthreads();
    LOAD_FRAGS(0, s0, 0);

    for (int kt = 0; kt < KT; kt++) {
        const uint32_t stage_cur = s0 + (kt % NST) * STG;
        const uint32_t stage_nxt = s0 + ((kt + 1) % NST) * STG;
        #pragma unroll
        for (int ks = 0; ks < 4; ks++) {
            const int cur = ks & 1, nxt = cur ^ 1;
            if (ks == 3) {
                if (kt + 1 < KT) {
                    CP_WAIT1();
                    __syncthreads();
                    LOAD_FRAGS(nxt, stage_nxt, 0);
                }
            } else {
                LOAD_FRAGS(nxt, stage_cur, (ks + 1) * 32);
            }
            if (ks == 0) {
                if (kt + 2 < KT) load_stage(s0, (kt + 2) % NST, kt + 2, tid, Ab, Bb);
                else             CP_COMMIT();    // keep pending-group count exact
            }
            #pragma unroll
            for (int mi = 0; mi < 4; mi++)
                #pragma unroll
                for (int ni = 0; ni < 8; ni++)
                    MMA16816(c[mi][ni], af[cur][mi], bf[cur][ni][0], bf[cur][ni][1]);
        }
    }
    #undef LOAD_FRAGS

    if (zq < 0) {
        // full tile: fp32 direct to C
        float* Cb = C + (size_t)(ty * 128 + wm) * MDIM + tx * 128 + wn;
        #pragma unroll
        for (int mi = 0; mi < 4; mi++) {
            #pragma unroll
            for (int ni = 0; ni < 8; ni++) {
                const int col = ni * 8 + 2 * t4;
                *reinterpret_cast<float2*>(Cb + (size_t)(mi * 16 + g    ) * MDIM + col) =
                    make_float2(c[mi][ni][0], c[mi][ni][1]);
                *reinterpret_cast<float2*>(Cb + (size_t)(mi * 16 + g + 8) * MDIM + col) =
                    make_float2(c[mi][ni][2], c[mi][ni][3]);
            }
        }
    } else {
        // quarter tile: fp16 partial to plane zq (row-local within tail region)
        __half* Pb = P + (size_t)zq * TAIL_ROWS * MDIM
                       + (size_t)((ty - 18) * 128 + wm) * MDIM + tx * 128 + wn;
        #pragma unroll
        for (int mi = 0; mi < 4; mi++) {
            #pragma unroll
            for (int ni = 0; ni < 8; ni++) {
                const int col = ni * 8 + 2 * t4;
                __half2 h0 = __floats2half2_rn(c[mi][ni][0], c[mi][ni][1]);
                __half2 h1 = __floats2half2_rn(c[mi][ni][2], c[mi][ni][3]);
                *reinterpret_cast<__half2*>(Pb + (size_t)(mi * 16 + g    ) * MDIM + col) = h0;
                *reinterpret_cast<__half2*>(Pb + (size_t)(mi * 16 + g + 8) * MDIM + col) = h1;
            }
        }
    }
}

// ===========================================================================
// Launch: input, SU, SV, grid, Qidxs (metadata order)
// ===========================================================================
extern "C" void kernel_launch(void* const* d_in, const int* in_sizes, int n_in,
                              void* d_out, int out_size) {
    const float* input = (const float*)d_in[0];
    const float* SU    = (const float*)d_in[1];
    const float* SV    = (const float*)d_in[2];
    const float* grid  = (const float*)d_in[3];
    const int*   qidxs = (const int*)  d_in[4];
    float* out = (float*)d_out;

    __half* Xh = nullptr;
    __half* W  = nullptr;
    __half* P  = nullptr;
    cudaGetSymbolAddress((void**)&Xh, g_Xh);
    cudaGetSymbolAddress((void**)&W,  g_W);
    cudaGetSymbolAddress((void**)&P,  g_P);

    cudaFuncSetAttribute(gemm_fp16, cudaFuncAttributeMaxDynamicSharedMemorySize, GEMM_SMEM);

    // 1. dequantize codebook -> W (fp16)
    dequant_kernel<<<NCODE / 512, 256>>>(grid, qidxs, W);

    // 2. Xh = fp16( FWHT(input * SU) / 64 )
    fwht_su_kernel<<<ROWS_T, 256>>>(input, SU, Xh);

    // 3. out tiles: 576 full-K CTAs first, then 1792 quarter-K CTAs (tail split)
    gemm_fp16<<<FULL_TILES + 4 * TAIL_TILES, 128, GEMM_SMEM>>>(Xh, W, out, P);

    // 4. out = FWHT(C | sum planes) * SV / 64
    fwht_sv_kernel<<<ROWS_T, 256>>>(out, P, out, SV);
}